// round 15
// baseline (speedup 1.0000x reference)
#include <cuda_runtime.h>
#include <math_constants.h>
#include <cstdint>

#define Bb 2048
#define Tt 200
#define Hh 256
#define Kk 8
#define GBv 4          // batches per fused block
#define AST 260        // A smem stride (floats): conflict-free a-frag reads

typedef unsigned long long ull;

// scratch (no allocs allowed)
__device__ float    g_WkT[Hh * Hh];
__device__ float    g_M[Hh * Hh];      // (Wq @ Wk^T)[m][i]
__device__ float    g_d[Hh];           // Wk @ bq
__device__ float    g_u[Hh];           // Wq @ bk
__device__ float    g_s0[1];           // bk . bq
__device__ float    g_R[Bb * Hh];
__device__ float    g_cb[Bb];
__device__ unsigned g_Bfrag[Hh * Hh];  // frag-packed tf32 Wv (uint2 per (kt,ntile,lane))

// ---- packed f32x2 helpers ----
__device__ __forceinline__ ull pk2(float x, float y) {
    ull r; asm("mov.b64 %0,{%1,%2};" : "=l"(r) : "f"(x), "f"(y)); return r;
}
__device__ __forceinline__ void upk2(ull v, float& x, float& y) {
    asm("mov.b64 {%0,%1},%2;" : "=f"(x), "=f"(y) : "l"(v));
}
__device__ __forceinline__ void fma2(ull& d, ull a, ull b) {
    asm("fma.rn.f32x2 %0,%1,%2,%0;" : "+l"(d) : "l"(a), "l"(b));
}
__device__ __forceinline__ unsigned tf32c(float f) {
    unsigned r; asm("cvt.rna.tf32.f32 %0, %1;" : "=r"(r) : "f"(f)); return r;
}
__device__ __forceinline__ void mma_tf32(float c[4], unsigned a0, unsigned a1,
                                         unsigned a2, unsigned a3,
                                         unsigned b0, unsigned b1) {
    asm volatile(
        "mma.sync.aligned.m16n8k8.row.col.f32.tf32.tf32.f32 "
        "{%0,%1,%2,%3},{%4,%5,%6,%7},{%8,%9},{%0,%1,%2,%3};"
        : "+f"(c[0]), "+f"(c[1]), "+f"(c[2]), "+f"(c[3])
        : "r"(a0), "r"(a1), "r"(a2), "r"(a3), "r"(b0), "r"(b1));
}

// ---------------------------------------------------------------------------
// Kernel 1 (fused prep): blocks [0,64) transpose Wk; blocks [64,192) pack Wv
// into per-lane tf32 B-fragments (uint2 per (kt, ntile, lane)).
// ---------------------------------------------------------------------------
__global__ void __launch_bounds__(256) prep_kernel(
    const float* __restrict__ Wk, const float* __restrict__ Wv) {
    const int tid = threadIdx.x;
    if (blockIdx.x < 64) {
        __shared__ float tile[32][33];
        int bx = blockIdx.x & 7, by = blockIdx.x >> 3;
        int tx = tid & 31, ty = tid >> 5;          // 32 x 8
        int x = bx * 32 + tx;
        int y = by * 32 + ty;
        #pragma unroll
        for (int j = 0; j < 32; j += 8)
            tile[ty + j][tx] = Wk[(size_t)(y + j) * Hh + x];
        __syncthreads();
        int xo = by * 32 + tx;
        int yo = bx * 32 + ty;
        #pragma unroll
        for (int j = 0; j < 32; j += 8)
            g_WkT[(size_t)(yo + j) * Hh + xo] = tile[tx][ty + j];
    } else {
        int idx  = (blockIdx.x - 64) * 256 + tid;   // 0 .. 32767
        int kt   = idx >> 10;
        int rem  = idx & 1023;
        int ntg  = rem >> 5;
        int lane = rem & 31;
        int g = lane >> 2, tg = lane & 3;
        int col = ntg * 8 + g;
        unsigned b0 = tf32c(Wv[(size_t)(kt * 8 + tg) * Hh + col]);
        unsigned b1 = tf32c(Wv[(size_t)(kt * 8 + tg + 4) * Hh + col]);
        uint2 v; v.x = b0; v.y = b1;
        *(uint2*)&g_Bfrag[idx * 2] = v;
    }
}

// ---------------------------------------------------------------------------
// Kernel 1b (prep2): M = Wq @ Wk^T, d = Wk @ bq, u = Wq @ bk, s0 = bk.bq.
// ---------------------------------------------------------------------------
__global__ void __launch_bounds__(256) prep2_kernel(
    const float* __restrict__ Wq, const float* __restrict__ bq,
    const float* __restrict__ bk) {
    __shared__ float wqs[Hh][4];
    __shared__ float bqs[Hh];
    __shared__ float bks[Hh];
    const int tid  = threadIdx.x;
    const int lane = tid & 31;
    const int wid  = tid >> 5;
    const int m0   = blockIdx.x * 4;

    #pragma unroll
    for (int mm = 0; mm < 4; mm++)
        wqs[tid][mm] = Wq[(size_t)(m0 + mm) * Hh + tid];
    bqs[tid] = bq[tid];
    bks[tid] = bk[tid];
    __syncthreads();

    ull a01 = pk2(0.f, 0.f), a23 = pk2(0.f, 0.f);
    float accd = 0.f;
    #pragma unroll 16
    for (int h = 0; h < Hh; h++) {
        float w = g_WkT[(size_t)h * Hh + tid];
        ull ww = pk2(w, w);
        ulonglong2 A = *(const ulonglong2*)&wqs[h][0];
        fma2(a01, A.x, ww);
        fma2(a23, A.y, ww);
        accd += w * bqs[h];
    }
    float m01a, m01b, m23a, m23b;
    upk2(a01, m01a, m01b); upk2(a23, m23a, m23b);
    g_M[(size_t)(m0 + 0) * Hh + tid] = m01a;
    g_M[(size_t)(m0 + 1) * Hh + tid] = m01b;
    g_M[(size_t)(m0 + 2) * Hh + tid] = m23a;
    g_M[(size_t)(m0 + 3) * Hh + tid] = m23b;
    if (blockIdx.x == 0) g_d[tid] = accd;

    if (wid == 0) {
        #pragma unroll
        for (int mm = 0; mm < 4; mm++) {
            float s = 0.f;
            for (int h = lane; h < Hh; h += 32) s += wqs[h][mm] * bks[h];
            #pragma unroll
            for (int o = 16; o; o >>= 1) s += __shfl_xor_sync(0xffffffffu, s, o);
            if (lane == 0) g_u[m0 + mm] = s;
        }
    }
    if (blockIdx.x == 0 && wid == 1) {
        float s = 0.f;
        for (int h = lane; h < Hh; h += 32) s += bks[h] * bqs[h];
        #pragma unroll
        for (int o = 16; o; o >>= 1) s += __shfl_xor_sync(0xffffffffu, s, o);
        if (lane == 0) g_s0[0] = s;
    }
}

// ---------------------------------------------------------------------------
// Kernel 2: 8 batches/block (256 blocks): r = cs @ M + d, cb = cs.u + s0.
// ---------------------------------------------------------------------------
__global__ void __launch_bounds__(256) proj_kernel(
    const float* __restrict__ cs) {
    __shared__ float cs_s[Hh][8];
    __shared__ float us[Hh];
    const int j  = threadIdx.x;
    const int b0 = blockIdx.x * 8;

    #pragma unroll
    for (int m = 0; m < 8; m++) cs_s[j][m] = cs[(size_t)(b0 + m) * Hh + j];
    us[j] = g_u[j];
    __syncthreads();

    ull acc[4];
    const float dj = g_d[j];
    const ull binit = pk2(dj, dj);
    #pragma unroll
    for (int q = 0; q < 4; q++) acc[q] = binit;
    #pragma unroll 8
    for (int m = 0; m < Hh; m++) {
        float w = g_M[(size_t)m * Hh + j];
        ull ww = pk2(w, w);
        ulonglong2 A = *(const ulonglong2*)&cs_s[m][0];
        ulonglong2 B = *(const ulonglong2*)&cs_s[m][4];
        fma2(acc[0], A.x, ww); fma2(acc[1], A.y, ww);
        fma2(acc[2], B.x, ww); fma2(acc[3], B.y, ww);
    }
    #pragma unroll
    for (int q = 0; q < 4; q++) {
        float a, b;
        upk2(acc[q], a, b);
        g_R[(size_t)(b0 + 2 * q) * Hh + j]     = a;
        g_R[(size_t)(b0 + 2 * q + 1) * Hh + j] = b;
    }
    if (j < 8) {
        float s = g_s0[0];
        for (int m = 0; m < Hh; m++) s += cs_s[m][j] * us[m];
        g_cb[b0 + j] = s;
    }
}

// ---------------------------------------------------------------------------
// Kernel 3 (FUSED): per block, 4 batches: [score -> top-8 -> attn/selected]
// sequentially, keeping top-8 in smem; then gathered-V tf32 mma for all 4.
// ---------------------------------------------------------------------------
__global__ void __launch_bounds__(256) fused_kernel(
    const float* __restrict__ ss, const unsigned int* __restrict__ mask,
    const float* __restrict__ bv, float* __restrict__ out) {
    __shared__ unsigned AsU[32 * AST];
    __shared__ float r_s[Hh];
    __shared__ float msc[256];
    __shared__ int   cidx[224];
    __shared__ unsigned bal[8];
    __shared__ int   redi[8];
    __shared__ int   i_bcast;
    __shared__ int   s_idx[32];
    __shared__ float s_w[32];
    __shared__ float bvs[Hh];

    const int tid  = threadIdx.x;
    const int lane = tid & 31;
    const int wid  = tid >> 5;
    const int b0   = blockIdx.x * GBv;

    bvs[tid] = bv[tid];

    // ================= SCORE PHASE: 4 batches sequentially =================
    for (int gb = 0; gb < GBv; gb++) {
        const int b = b0 + gb;
        const float* ssb = ss + (size_t)b * Tt * Hh;

        r_s[tid] = __ldg(&g_R[(size_t)b * Hh + tid]);
        const float cb = g_cb[b];

        int mt = 0;
        if (tid < Tt) mt = (mask[(size_t)b * Tt + tid] != 0u) ? 1 : 0;
        int sv = mt;
        #pragma unroll
        for (int o = 16; o; o >>= 1) sv += __shfl_xor_sync(0xffffffffu, sv, o);
        if (lane == 0) redi[wid] = sv;
        __syncthreads();
        if (wid == 0) {
            int v = (lane < 8) ? redi[lane] : 0;
            #pragma unroll
            for (int o = 4; o; o >>= 1) v += __shfl_xor_sync(0xffffffffu, v, o);
            if (lane == 0) i_bcast = v;
        }
        if (tid < Tt) out[(size_t)Bb * Hh + (size_t)b * Tt + tid] = 0.f;
        __syncthreads();
        const int lim = i_bcast - 1;
        const bool h = (tid < Tt) && mt && (tid < lim);

        bal[wid] = __ballot_sync(0xffffffffu, h);
        msc[tid] = -CUDART_INF_F;
        __syncthreads();
        int base = 0;
        #pragma unroll
        for (int w2 = 0; w2 < 8; w2++) base += (w2 < wid) ? __popc(bal[w2]) : 0;
        int nv = 0;
        #pragma unroll
        for (int w2 = 0; w2 < 8; w2++) nv += __popc(bal[w2]);
        if (h) cidx[base + __popc(bal[wid] & ((1u << lane) - 1u))] = tid;
        __syncthreads();

        float rr[8];
        #pragma unroll
        for (int e = 0; e < 8; e++) rr[e] = r_s[lane * 8 + e];

        int ci = wid;
        for (; ci + 24 < nv; ci += 32) {
            int tu[4];
            float d[4];
            #pragma unroll
            for (int u = 0; u < 4; u++) {
                tu[u] = cidx[ci + 8 * u];
                const float4* rw = (const float4*)(ssb + (size_t)tu[u] * Hh);
                float4 a = __ldcs(rw + lane * 2), c = __ldcs(rw + lane * 2 + 1);
                d[u] = a.x * rr[0] + a.y * rr[1] + a.z * rr[2] + a.w * rr[3]
                     + c.x * rr[4] + c.y * rr[5] + c.z * rr[6] + c.w * rr[7];
            }
            d[0] += __shfl_xor_sync(0xffffffffu, d[0], 16);
            d[1] += __shfl_xor_sync(0xffffffffu, d[1], 16);
            d[2] += __shfl_xor_sync(0xffffffffu, d[2], 16);
            d[3] += __shfl_xor_sync(0xffffffffu, d[3], 16);
            float e01 = (lane < 16) ? d[0] : d[1];
            float e23 = (lane < 16) ? d[2] : d[3];
            #pragma unroll
            for (int o = 8; o; o >>= 1) {
                e01 += __shfl_xor_sync(0xffffffffu, e01, o);
                e23 += __shfl_xor_sync(0xffffffffu, e23, o);
            }
            if (lane == 0)  { msc[tu[0]] = (e01 + cb) * 0.0625f;
                              msc[tu[2]] = (e23 + cb) * 0.0625f; }
            if (lane == 16) { msc[tu[1]] = (e01 + cb) * 0.0625f;
                              msc[tu[3]] = (e23 + cb) * 0.0625f; }
        }
        for (; ci < nv; ci += 8) {
            int t = cidx[ci];
            const float4* rw = (const float4*)(ssb + (size_t)t * Hh);
            float4 a = __ldcs(rw + lane * 2), c = __ldcs(rw + lane * 2 + 1);
            float d = a.x * rr[0] + a.y * rr[1] + a.z * rr[2] + a.w * rr[3]
                    + c.x * rr[4] + c.y * rr[5] + c.z * rr[6] + c.w * rr[7];
            #pragma unroll
            for (int o = 16; o; o >>= 1) d += __shfl_xor_sync(0xffffffffu, d, o);
            if (lane == 0) msc[t] = (d + cb) * 0.0625f;
        }
        __syncthreads();

        if (wid == 0) {
            float v[7];
            #pragma unroll
            for (int j = 0; j < 7; j++) v[j] = msc[lane + 32 * j];

            float kval[8]; int kidx[8];
            #pragma unroll
            for (int k = 0; k < Kk; k++) {
                float bv_ = -CUDART_INF_F; int bi = 0x7fffffff;
                #pragma unroll
                for (int j = 0; j < 7; j++) {
                    int ix = lane + 32 * j;
                    if (v[j] > bv_ || (v[j] == bv_ && ix < bi)) { bv_ = v[j]; bi = ix; }
                }
                float wv_ = bv_; int wi = bi;
                #pragma unroll
                for (int o = 16; o; o >>= 1) {
                    float ov = __shfl_xor_sync(0xffffffffu, wv_, o);
                    int   oi = __shfl_xor_sync(0xffffffffu, wi, o);
                    if (ov > wv_ || (ov == wv_ && oi < wi)) { wv_ = ov; wi = oi; }
                }
                kval[k] = wv_; kidx[k] = wi;
                #pragma unroll
                for (int j = 0; j < 7; j++)
                    if (wi == lane + 32 * j) v[j] = -CUDART_INF_F;
            }

            const float kmax = kval[0];
            float p[8]; float sum = 0.f;
            #pragma unroll
            for (int k = 0; k < Kk; k++) {
                bool val = kval[k] > -1e30f;
                p[k] = val ? __expf(kval[k] - kmax) : 0.f;
                sum += p[k];
            }
            const float inv = 1.f / fmaxf(sum, 1.1920929e-07f);

            float myv = kval[0], myp = p[0]; int myi = kidx[0];
            #pragma unroll
            for (int k = 1; k < Kk; k++)
                if (lane == k) { myv = kval[k]; myp = p[k]; myi = kidx[k]; }

            if (lane < Kk) {
                bool val = myv > -1e30f;
                float w = val ? myp * inv : 0.f;
                s_idx[gb * Kk + lane] = val ? myi : -1;
                s_w[gb * Kk + lane]   = w;
                out[(size_t)Bb * Hh + (size_t)Bb * Tt + (size_t)b * Kk + lane] =
                    val ? (float)myi : -1.f;
                if (val) out[(size_t)Bb * Hh + (size_t)b * Tt + myi] = w;
            }
        }
        __syncthreads();
    }

    // ================= V PHASE (round-7 mma, selections from smem) =========
    #pragma unroll 4
    for (int r = 0; r < 32; r++) {
        int t = s_idx[r];
        float val = 0.f;
        if (t >= 0)
            val = ss[((size_t)(b0 + (r >> 3)) * Tt + t) * Hh + tid];
        AsU[r * AST + tid] = tf32c(val);
    }
    __syncthreads();

    const int wm = wid & 1;        // m-tile 0..1
    const int wn = wid >> 1;       // n quarter 0..3
    const int g  = lane >> 2;
    const int tg = lane & 3;

    float c[8][4];
    #pragma unroll
    for (int nt = 0; nt < 8; nt++)
        #pragma unroll
        for (int q = 0; q < 4; q++) c[nt][q] = 0.f;

    const int arow = 16 * wm + g;
    const uint2* bp = (const uint2*)g_Bfrag;
    #pragma unroll 2
    for (int kt = 0; kt < 32; kt++) {
        int kabs = kt * 8;
        unsigned a0 = AsU[arow * AST + kabs + tg];
        unsigned a1 = AsU[(arow + 8) * AST + kabs + tg];
        unsigned a2 = AsU[arow * AST + kabs + tg + 4];
        unsigned a3 = AsU[(arow + 8) * AST + kabs + tg + 4];
        const uint2* bq_ = bp + ((size_t)kt * 32 + wn * 8) * 32 + lane;
        #pragma unroll
        for (int nt = 0; nt < 8; nt++) {
            uint2 bb = __ldg(bq_ + nt * 32);
            mma_tf32(c[nt], a0, a1, a2, a3, bb.x, bb.y);
        }
    }

    const int L0 = 2 * wm;
    const float w0 = s_w[L0 * 8 + g];
    const float w1 = s_w[(L0 + 1) * 8 + g];
    #pragma unroll
    for (int nt = 0; nt < 8; nt++) {
        int cbase = wn * 64 + nt * 8 + 2 * tg;
        float bv0 = bvs[cbase], bv1 = bvs[cbase + 1];
        float v0 = w0 * fmaxf(c[nt][0] + bv0, 0.f);
        float v1 = w0 * fmaxf(c[nt][1] + bv1, 0.f);
        float v2 = w1 * fmaxf(c[nt][2] + bv0, 0.f);
        float v3 = w1 * fmaxf(c[nt][3] + bv1, 0.f);
        #pragma unroll
        for (int o = 4; o <= 16; o <<= 1) {
            v0 += __shfl_xor_sync(0xffffffffu, v0, o);
            v1 += __shfl_xor_sync(0xffffffffu, v1, o);
            v2 += __shfl_xor_sync(0xffffffffu, v2, o);
            v3 += __shfl_xor_sync(0xffffffffu, v3, o);
        }
        if (g == 0) {
            out[(size_t)(b0 + L0) * Hh + cbase]         = v0;
            out[(size_t)(b0 + L0) * Hh + cbase + 1]     = v1;
            out[(size_t)(b0 + L0 + 1) * Hh + cbase]     = v2;
            out[(size_t)(b0 + L0 + 1) * Hh + cbase + 1] = v3;
        }
    }
}

// ---------------------------------------------------------------------------
extern "C" void kernel_launch(void* const* d_in, const int* in_sizes, int n_in,
                              void* d_out, int out_size) {
    const float* cs = (const float*)d_in[0];
    const float* ss = (const float*)d_in[1];
    const unsigned int* mask = (const unsigned int*)d_in[2];
    const float* Wq = (const float*)d_in[3];
    const float* bq = (const float*)d_in[4];
    const float* Wk = (const float*)d_in[5];
    const float* bk = (const float*)d_in[6];
    const float* Wv = (const float*)d_in[7];
    const float* bv = (const float*)d_in[8];
    float* out = (float*)d_out;

    prep_kernel<<<192, 256>>>(Wk, Wv);
    prep2_kernel<<<64, 256>>>(Wq, bq, bk);
    proj_kernel<<<Bb / 8, 256>>>(cs);
    fused_kernel<<<Bb / GBv, 256>>>(ss, mask, bv, out);
}

// round 16
// speedup vs baseline: 1.1397x; 1.1397x over previous
#include <cuda_runtime.h>
#include <math_constants.h>
#include <cstdint>

#define Bb 2048
#define Tt 200
#define Hh 256
#define Kk 8
#define GBv 4          // batches per v_kernel block
#define AST 260        // A smem stride (floats): conflict-free a-frag reads

typedef unsigned long long ull;

// scratch (no allocs allowed)
__device__ float    g_R[Bb * Hh];
__device__ float    g_cb[Bb];
__device__ int      g_selidx[Bb * Kk];
__device__ float    g_selw[Bb * Kk];
__device__ unsigned g_Bfrag[Hh * Hh];  // frag-packed tf32 Wv (uint2 per (kt,ntile,lane))

// ---- packed f32x2 helpers ----
__device__ __forceinline__ ull pk2(float x, float y) {
    ull r; asm("mov.b64 %0,{%1,%2};" : "=l"(r) : "f"(x), "f"(y)); return r;
}
__device__ __forceinline__ void upk2(ull v, float& x, float& y) {
    asm("mov.b64 {%0,%1},%2;" : "=f"(x), "=f"(y) : "l"(v));
}
__device__ __forceinline__ void fma2(ull& d, ull a, ull b) {
    asm("fma.rn.f32x2 %0,%1,%2,%0;" : "+l"(d) : "l"(a), "l"(b));
}
__device__ __forceinline__ unsigned tf32c(float f) {
    unsigned r; asm("cvt.rna.tf32.f32 %0, %1;" : "=r"(r) : "f"(f)); return r;
}
__device__ __forceinline__ void mma_tf32(float c[4], unsigned a0, unsigned a1,
                                         unsigned a2, unsigned a3,
                                         unsigned b0, unsigned b1) {
    asm volatile(
        "mma.sync.aligned.m16n8k8.row.col.f32.tf32.tf32.f32 "
        "{%0,%1,%2,%3},{%4,%5,%6,%7},{%8,%9},{%0,%1,%2,%3};"
        : "+f"(c[0]), "+f"(c[1]), "+f"(c[2]), "+f"(c[3])
        : "r"(a0), "r"(a1), "r"(a2), "r"(a3), "r"(b0), "r"(b1));
}

// ---------------------------------------------------------------------------
// Launch 1 (MEGA): blocks [0,128) pack Wv into tf32 B-fragments;
// blocks [128,384) do the q/r projection for 8 batches each, with an inline
// smem transpose of Wk (no separate transpose kernel, no extra launch).
// ---------------------------------------------------------------------------
__global__ void __launch_bounds__(256) mega_kernel(
    const float* __restrict__ cs, const float* __restrict__ Wq,
    const float* __restrict__ Wk, const float* __restrict__ Wv,
    const float* __restrict__ bq, const float* __restrict__ bk) {
    const int tid = threadIdx.x;

    if (blockIdx.x < 128) {
        // ---- Wv B-fragment packing (identical to validated prep) ----
        int idx  = blockIdx.x * 256 + tid;   // 0 .. 32767
        int kt   = idx >> 10;
        int rem  = idx & 1023;
        int ntg  = rem >> 5;
        int lane = rem & 31;
        int g = lane >> 2, tg = lane & 3;
        int col = ntg * 8 + g;
        unsigned b0 = tf32c(Wv[(size_t)(kt * 8 + tg) * Hh + col]);
        unsigned b1 = tf32c(Wv[(size_t)(kt * 8 + tg + 4) * Hh + col]);
        uint2 v; v.x = b0; v.y = b1;
        *(uint2*)&g_Bfrag[idx * 2] = v;
        return;
    }

    // ---- projection: q = cs@Wq + bq ; r = Wk@q ; cb = bk.q ----
    __shared__ float cs_s[Hh][8];
    __shared__ float q_s[Hh][8];
    __shared__ float wkts[32][265];     // transposed Wk chunk, conflict-free
    const int j  = tid;
    const int b0 = (blockIdx.x - 128) * 8;

    #pragma unroll
    for (int m = 0; m < 8; m++) cs_s[j][m] = cs[(size_t)(b0 + m) * Hh + j];
    __syncthreads();

    ull acc[4];
    const float bqj = bq[j];
    const ull binit = pk2(bqj, bqj);
    #pragma unroll
    for (int q = 0; q < 4; q++) acc[q] = binit;
    #pragma unroll 8
    for (int i = 0; i < Hh; i++) {
        float w = Wq[(size_t)i * Hh + j];
        ull ww = pk2(w, w);
        ulonglong2 A = *(const ulonglong2*)&cs_s[i][0];
        ulonglong2 B = *(const ulonglong2*)&cs_s[i][4];
        fma2(acc[0], A.x, ww); fma2(acc[1], A.y, ww);
        fma2(acc[2], B.x, ww); fma2(acc[3], B.y, ww);
    }
    #pragma unroll
    for (int q = 0; q < 4; q++) upk2(acc[q], q_s[j][2 * q], q_s[j][2 * q + 1]);
    __syncthreads();

    // cb while pass-2 staging warms up
    if (j < 8) {
        float s = 0.f;
        for (int i = 0; i < Hh; i++) s += bk[i] * q_s[i][j];
        g_cb[b0 + j] = s;
    }

    // pass 2: r[o=j] = sum_i Wk[o][i] * q[i], via 8 chunked inline transposes
    #pragma unroll
    for (int q = 0; q < 4; q++) acc[q] = pk2(0.f, 0.f);
    for (int ic = 0; ic < 8; ic++) {
        __syncthreads();
        // stage wkts[ii][o] = Wk[o][ic*32+ii] (coalesced LDG, conflict-free STS)
        #pragma unroll
        for (int p = 0; p < 32; p++) {
            int li = p * 256 + tid;
            int o  = li >> 5;
            int ii = li & 31;
            wkts[ii][o] = Wk[(size_t)o * Hh + ic * 32 + ii];
        }
        __syncthreads();
        #pragma unroll
        for (int ii = 0; ii < 32; ii++) {
            float w = wkts[ii][j];
            ull ww = pk2(w, w);
            int i = ic * 32 + ii;
            ulonglong2 A = *(const ulonglong2*)&q_s[i][0];
            ulonglong2 B = *(const ulonglong2*)&q_s[i][4];
            fma2(acc[0], A.x, ww); fma2(acc[1], A.y, ww);
            fma2(acc[2], B.x, ww); fma2(acc[3], B.y, ww);
        }
    }
    #pragma unroll
    for (int q = 0; q < 4; q++) {
        float a, b;
        upk2(acc[q], a, b);
        g_R[(size_t)(b0 + 2 * q) * Hh + j]     = a;
        g_R[(size_t)(b0 + 2 * q + 1) * Hh + j] = b;
    }
}

// ---------------------------------------------------------------------------
// Launch 2: compact valid rows (mask && t < lim) -> score ONLY those rows ->
// top-8 -> attn/selected/scratch. (byte-identical to validated version)
// ---------------------------------------------------------------------------
__global__ void __launch_bounds__(256) score_kernel(
    const float* __restrict__ ss, const unsigned int* __restrict__ mask,
    float* __restrict__ out) {
    __shared__ float r_s[Hh];
    __shared__ float msc[256];
    __shared__ int   cidx[224];
    __shared__ unsigned bal[8];
    __shared__ int   redi[8];
    __shared__ int   i_bcast;

    const int tid  = threadIdx.x;
    const int lane = tid & 31;
    const int wid  = tid >> 5;
    const int b    = blockIdx.x;
    const float* ssb = ss + (size_t)b * Tt * Hh;

    r_s[tid] = __ldg(&g_R[(size_t)b * Hh + tid]);
    const float cb = g_cb[b];

    int mt = 0;
    if (tid < Tt) mt = (mask[(size_t)b * Tt + tid] != 0u) ? 1 : 0;
    int sv = mt;
    #pragma unroll
    for (int o = 16; o; o >>= 1) sv += __shfl_xor_sync(0xffffffffu, sv, o);
    if (lane == 0) redi[wid] = sv;
    __syncthreads();
    if (wid == 0) {
        int v = (lane < 8) ? redi[lane] : 0;
        #pragma unroll
        for (int o = 4; o; o >>= 1) v += __shfl_xor_sync(0xffffffffu, v, o);
        if (lane == 0) i_bcast = v;
    }
    if (tid < Tt) out[(size_t)Bb * Hh + (size_t)b * Tt + tid] = 0.f;
    __syncthreads();
    const int lim = i_bcast - 1;
    const bool h = (tid < Tt) && mt && (tid < lim);

    bal[wid] = __ballot_sync(0xffffffffu, h);
    msc[tid] = -CUDART_INF_F;
    __syncthreads();
    int base = 0;
    #pragma unroll
    for (int w2 = 0; w2 < 8; w2++) base += (w2 < wid) ? __popc(bal[w2]) : 0;
    int nv = 0;
    #pragma unroll
    for (int w2 = 0; w2 < 8; w2++) nv += __popc(bal[w2]);
    if (h) cidx[base + __popc(bal[wid] & ((1u << lane) - 1u))] = tid;
    __syncthreads();

    float rr[8];
    #pragma unroll
    for (int e = 0; e < 8; e++) rr[e] = r_s[lane * 8 + e];

    int ci = wid;
    for (; ci + 24 < nv; ci += 32) {
        int tu[4];
        float d[4];
        #pragma unroll
        for (int u = 0; u < 4; u++) {
            tu[u] = cidx[ci + 8 * u];
            const float4* rw = (const float4*)(ssb + (size_t)tu[u] * Hh);
            float4 a = __ldcs(rw + lane * 2), c = __ldcs(rw + lane * 2 + 1);
            d[u] = a.x * rr[0] + a.y * rr[1] + a.z * rr[2] + a.w * rr[3]
                 + c.x * rr[4] + c.y * rr[5] + c.z * rr[6] + c.w * rr[7];
        }
        d[0] += __shfl_xor_sync(0xffffffffu, d[0], 16);
        d[1] += __shfl_xor_sync(0xffffffffu, d[1], 16);
        d[2] += __shfl_xor_sync(0xffffffffu, d[2], 16);
        d[3] += __shfl_xor_sync(0xffffffffu, d[3], 16);
        float e01 = (lane < 16) ? d[0] : d[1];
        float e23 = (lane < 16) ? d[2] : d[3];
        #pragma unroll
        for (int o = 8; o; o >>= 1) {
            e01 += __shfl_xor_sync(0xffffffffu, e01, o);
            e23 += __shfl_xor_sync(0xffffffffu, e23, o);
        }
        if (lane == 0)  { msc[tu[0]] = (e01 + cb) * 0.0625f;
                          msc[tu[2]] = (e23 + cb) * 0.0625f; }
        if (lane == 16) { msc[tu[1]] = (e01 + cb) * 0.0625f;
                          msc[tu[3]] = (e23 + cb) * 0.0625f; }
    }
    for (; ci < nv; ci += 8) {
        int t = cidx[ci];
        const float4* rw = (const float4*)(ssb + (size_t)t * Hh);
        float4 a = __ldcs(rw + lane * 2), c = __ldcs(rw + lane * 2 + 1);
        float d = a.x * rr[0] + a.y * rr[1] + a.z * rr[2] + a.w * rr[3]
                + c.x * rr[4] + c.y * rr[5] + c.z * rr[6] + c.w * rr[7];
        #pragma unroll
        for (int o = 16; o; o >>= 1) d += __shfl_xor_sync(0xffffffffu, d, o);
        if (lane == 0) msc[t] = (d + cb) * 0.0625f;
    }
    __syncthreads();

    if (wid == 0) {
        float v[7];
        #pragma unroll
        for (int j = 0; j < 7; j++) v[j] = msc[lane + 32 * j];

        float kval[8]; int kidx[8];
        #pragma unroll
        for (int k = 0; k < Kk; k++) {
            float bv_ = -CUDART_INF_F; int bi = 0x7fffffff;
            #pragma unroll
            for (int j = 0; j < 7; j++) {
                int ix = lane + 32 * j;
                if (v[j] > bv_ || (v[j] == bv_ && ix < bi)) { bv_ = v[j]; bi = ix; }
            }
            float wv_ = bv_; int wi = bi;
            #pragma unroll
            for (int o = 16; o; o >>= 1) {
                float ov = __shfl_xor_sync(0xffffffffu, wv_, o);
                int   oi = __shfl_xor_sync(0xffffffffu, wi, o);
                if (ov > wv_ || (ov == wv_ && oi < wi)) { wv_ = ov; wi = oi; }
            }
            kval[k] = wv_; kidx[k] = wi;
            #pragma unroll
            for (int j = 0; j < 7; j++)
                if (wi == lane + 32 * j) v[j] = -CUDART_INF_F;
        }

        const float kmax = kval[0];
        float p[8]; float sum = 0.f;
        #pragma unroll
        for (int k = 0; k < Kk; k++) {
            bool val = kval[k] > -1e30f;
            p[k] = val ? __expf(kval[k] - kmax) : 0.f;
            sum += p[k];
        }
        const float inv = 1.f / fmaxf(sum, 1.1920929e-07f);

        float myv = kval[0], myp = p[0]; int myi = kidx[0];
        #pragma unroll
        for (int k = 1; k < Kk; k++)
            if (lane == k) { myv = kval[k]; myp = p[k]; myi = kidx[k]; }

        if (lane < Kk) {
            bool val = myv > -1e30f;
            float w = val ? myp * inv : 0.f;
            g_selidx[b * Kk + lane] = val ? myi : -1;
            g_selw[b * Kk + lane]   = w;
            out[(size_t)Bb * Hh + (size_t)Bb * Tt + (size_t)b * Kk + lane] =
                val ? (float)myi : -1.f;
            if (val) out[(size_t)Bb * Hh + (size_t)b * Tt + myi] = w;
        }
    }
}

// ---------------------------------------------------------------------------
// Launch 3: sparse V projection via tf32 mma (EXACT round-7 structure).
// ---------------------------------------------------------------------------
__global__ void __launch_bounds__(256) v_kernel(
    const float* __restrict__ ss, const float* __restrict__ bv,
    float* __restrict__ out) {
    __shared__ unsigned AsU[32 * AST];
    __shared__ float swts[32];
    __shared__ int   sidx[32];
    __shared__ float bvs[Hh];

    const int tid  = threadIdx.x;
    const int lane = tid & 31;
    const int w    = tid >> 5;
    const int wm   = w & 1;        // m-tile 0..1
    const int wn   = w >> 1;       // n quarter 0..3
    const int g    = lane >> 2;
    const int tg   = lane & 3;
    const int b0   = blockIdx.x * GBv;

    if (tid < 32) {
        sidx[tid] = g_selidx[b0 * Kk + tid];
        swts[tid] = g_selw[b0 * Kk + tid];
    }
    bvs[tid] = bv[tid];
    __syncthreads();

    #pragma unroll 4
    for (int r = 0; r < 32; r++) {
        int t = sidx[r];
        float val = 0.f;
        if (t >= 0)
            val = ss[((size_t)(b0 + (r >> 3)) * Tt + t) * Hh + tid];
        AsU[r * AST + tid] = tf32c(val);
    }
    __syncthreads();

    float c[8][4];
    #pragma unroll
    for (int nt = 0; nt < 8; nt++)
        #pragma unroll
        for (int q = 0; q < 4; q++) c[nt][q] = 0.f;

    const int arow = 16 * wm + g;
    const uint2* bp = (const uint2*)g_Bfrag;
    #pragma unroll 2
    for (int kt = 0; kt < 32; kt++) {
        int kabs = kt * 8;
        unsigned a0 = AsU[arow * AST + kabs + tg];
        unsigned a1 = AsU[(arow + 8) * AST + kabs + tg];
        unsigned a2 = AsU[arow * AST + kabs + tg + 4];
        unsigned a3 = AsU[(arow + 8) * AST + kabs + tg + 4];
        const uint2* bq_ = bp + ((size_t)kt * 32 + wn * 8) * 32 + lane;
        #pragma unroll
        for (int nt = 0; nt < 8; nt++) {
            uint2 bb = __ldg(bq_ + nt * 32);
            mma_tf32(c[nt], a0, a1, a2, a3, bb.x, bb.y);
        }
    }

    const int L0 = 2 * wm;
    const float w0 = swts[L0 * 8 + g];
    const float w1 = swts[(L0 + 1) * 8 + g];
    #pragma unroll
    for (int nt = 0; nt < 8; nt++) {
        int cbase = wn * 64 + nt * 8 + 2 * tg;
        float bv0 = bvs[cbase], bv1 = bvs[cbase + 1];
        float v0 = w0 * fmaxf(c[nt][0] + bv0, 0.f);
        float v1 = w0 * fmaxf(c[nt][1] + bv1, 0.f);
        float v2 = w1 * fmaxf(c[nt][2] + bv0, 0.f);
        float v3 = w1 * fmaxf(c[nt][3] + bv1, 0.f);
        #pragma unroll
        for (int o = 4; o <= 16; o <<= 1) {
            v0 += __shfl_xor_sync(0xffffffffu, v0, o);
            v1 += __shfl_xor_sync(0xffffffffu, v1, o);
            v2 += __shfl_xor_sync(0xffffffffu, v2, o);
            v3 += __shfl_xor_sync(0xffffffffu, v3, o);
        }
        if (g == 0) {
            out[(size_t)(b0 + L0) * Hh + cbase]         = v0;
            out[(size_t)(b0 + L0) * Hh + cbase + 1]     = v1;
            out[(size_t)(b0 + L0 + 1) * Hh + cbase]     = v2;
            out[(size_t)(b0 + L0 + 1) * Hh + cbase + 1] = v3;
        }
    }
}

// ---------------------------------------------------------------------------
extern "C" void kernel_launch(void* const* d_in, const int* in_sizes, int n_in,
                              void* d_out, int out_size) {
    const float* cs = (const float*)d_in[0];
    const float* ss = (const float*)d_in[1];
    const unsigned int* mask = (const unsigned int*)d_in[2];
    const float* Wq = (const float*)d_in[3];
    const float* bq = (const float*)d_in[4];
    const float* Wk = (const float*)d_in[5];
    const float* bk = (const float*)d_in[6];
    const float* Wv = (const float*)d_in[7];
    const float* bv = (const float*)d_in[8];
    float* out = (float*)d_out;

    mega_kernel<<<128 + Bb / 8, 256>>>(cs, Wq, Wk, Wv, bq, bk);
    score_kernel<<<Bb, 256>>>(ss, mask, out);
    v_kernel<<<Bb / GBv, 256>>>(ss, bv, out);
}